// round 15
// baseline (speedup 1.0000x reference)
#include <cuda_runtime.h>
#include <cuda_bf16.h>
#include <cstdint>

#define TT 8
#define BB 32
#define CC_ 128
#define HW 1024
#define IMG 256
#define PLANE (BB*CC_*HW)
#define TOT (TT*PLANE)

#define KMEM 16
#define SIGMA 5.0e-6f

#define ICS 136                          // slab ic stride (bf16 elems)
#define WST 132                          // weight tile ic stride
#define WTE (128*WST)                    // elems per weight buffer
#define SLAB_E (10*34*ICS)               // 46240 bf16
#define CONVT_SMEM ((SLAB_E + 2*WTE)*2)  // 160064 B

__device__ float  g_bufL1[TOT];
__device__ __nv_bfloat16 g_bufS[TOT];    // spikes (0/1 exact in bf16)
__device__ float  g_bufC[TOT];
__device__ __nv_bfloat16 g_wsp[54*WTE];  // [layer*27 + tap*3+split][oc][WST]
__device__ double g_sums[CC_];
__device__ double g_sumsq[CC_];
__device__ float  g_meanA[2][CC_];
__device__ float  g_rstdA[2][CC_];
__device__ float  g_feat[BB*CC_];

// ---- packed f32x2 helpers (L1 exact conv) ----
__device__ __forceinline__ unsigned long long dup2(float v) {
    unsigned long long r; unsigned u = __float_as_uint(v);
    asm("mov.b64 %0, {%1, %1};" : "=l"(r) : "r"(u));
    return r;
}
__device__ __forceinline__ void fma2(unsigned long long& d,
                                     unsigned long long a, unsigned long long b) {
    asm("fma.rn.f32x2 %0, %1, %2, %0;" : "+l"(d) : "l"(a), "l"(b));
}
__device__ __forceinline__ unsigned long long add2(unsigned long long a,
                                                   unsigned long long b) {
    unsigned long long r;
    asm("add.rn.f32x2 %0, %1, %2;" : "=l"(r) : "l"(a), "l"(b));
    return r;
}
__device__ __forceinline__ unsigned long long mul2(unsigned long long a,
                                                   unsigned long long b) {
    unsigned long long r;
    asm("mul.rn.f32x2 %0, %1, %2;" : "=l"(r) : "l"(a), "l"(b));
    return r;
}
__device__ __forceinline__ float2 unp(unsigned long long v) {
    unsigned lo, hi;
    asm("mov.b64 {%0, %1}, %2;" : "=r"(lo), "=r"(hi) : "l"(v));
    return make_float2(__uint_as_float(lo), __uint_as_float(hi));
}

__device__ __forceinline__ float gnoise(unsigned gid, unsigned seed) {
    unsigned h = gid ^ (seed * 0x9E3779B9u);
    h ^= h >> 16; h *= 0x7feb352du;
    h ^= h >> 15; h *= 0x846ca68bu;
    h ^= h >> 16;
    int s = (int)((h & 255u) + ((h >> 8) & 255u) + ((h >> 16) & 255u) +
                  ((h >> 24) & 255u)) - 510;
    return (float)s * (1.0f / 147.8f);
}

__device__ __forceinline__ void cp16(void* dst_smem, const void* src) {
    uint32_t a = (uint32_t)__cvta_generic_to_shared(dst_smem);
    asm volatile("cp.async.cg.shared.global [%0], [%1], 16;" :: "r"(a), "l"(src));
}

// ============================================================================
// Weight prep: 3-way bf16 split (exact products vs binary spikes).
// ============================================================================
__global__ void prep_w(const float* __restrict__ w2, const float* __restrict__ w3) {
    int idx = blockIdx.x * 256 + threadIdx.x;
    if (idx >= 2 * 9 * CC_ * CC_) return;
    int ic = idx & 127;
    int oc = (idx >> 7) & 127;
    int rest = idx >> 14;
    int tap = rest % 9, layer = rest / 9;
    const float* w = layer ? w3 : w2;
    float v = w[(oc * CC_ + ic) * 9 + tap];
    __nv_bfloat16 b1 = __float2bfloat16_rn(v);
    float r1 = v - __bfloat162float(b1);
    __nv_bfloat16 b2 = __float2bfloat16_rn(r1);
    __nv_bfloat16 b3 = __float2bfloat16_rn(r1 - __bfloat162float(b2));
    size_t tb = ((size_t)layer * 27 + tap * 3) * WTE + (size_t)oc * WST;
    g_wsp[tb + ic] = b1;
    g_wsp[tb + WTE + ic] = b2;
    g_wsp[tb + 2 * WTE + ic] = b3;
    if (ic < 4) {
        __nv_bfloat16 z = __float2bfloat16_rn(0.f);
        g_wsp[tb + 128 + ic] = z;
        g_wsp[tb + WTE + 128 + ic] = z;
        g_wsp[tb + 2 * WTE + 128 + ic] = z;
    }
}

// ============================================================================
// Tensor-core member conv + FUSED per-channel stats.
// CTA: 1 img, 8 rows (256px), 128 oc. 512 thr / 16 warps (32oc x 64px).
// cp.async double-buffered weight staging overlaps MMA.
// ============================================================================
__global__ __launch_bounds__(512, 1)
void conv_t(const __nv_bfloat16* __restrict__ spk,
            const __nv_bfloat16* __restrict__ wsp, float* __restrict__ y) {
    extern __shared__ __nv_bfloat16 sm[];
    __nv_bfloat16* slab = sm;            // [10][34][ICS]
    __nv_bfloat16* wt = sm + SLAB_E;     // [2][128][WST]

    const int tid = threadIdx.x;
    const int img = blockIdx.y;
    const int r0 = blockIdx.x * 8;
    const int wid = tid >> 5, lane = tid & 31;
    const int ocg = (wid & 3) * 32;
    const int pxg = (wid >> 2) * 64;
    const __nv_bfloat16 z = __float2bfloat16_rn(0.f);

    // stage spike slab: bf16 global -> channel-last smem, halo zeros
    const __nv_bfloat16* sb = spk + (size_t)img * CC_ * HW;
    for (int job = tid; job < 128 * 10; job += 512) {
        int ic = job / 10, srow = job - 10 * ic;
        int gr = r0 + srow - 1;
        __nv_bfloat16* drow = slab + (srow * 34) * ICS + ic;
        if ((unsigned)gr < 32u) {
            const uint4* src = reinterpret_cast<const uint4*>(sb + ic * HW + gr * 32);
            drow[0] = z;
            #pragma unroll
            for (int c8 = 0; c8 < 4; c8++) {
                uint4 u = src[c8];
                const __nv_bfloat16* e = reinterpret_cast<const __nv_bfloat16*>(&u);
                #pragma unroll
                for (int k = 0; k < 8; k++) drow[(c8 * 8 + k + 1) * ICS] = e[k];
            }
            drow[33 * ICS] = z;
        } else {
            #pragma unroll
            for (int c = 0; c < 34; c++) drow[c * ICS] = z;
        }
    }

    auto stageW = [&](int s) {
        const float4* src = reinterpret_cast<const float4*>(wsp + (size_t)s * WTE);
        float4* dst = reinterpret_cast<float4*>(wt + (s & 1) * WTE);
        for (int i = tid; i < WTE / 8; i += 512) cp16(dst + i, src + i);
        asm volatile("cp.async.commit_group;" ::: "memory");
    };

    float d[2][8][4];
    #pragma unroll
    for (int mt = 0; mt < 2; mt++)
        #pragma unroll
        for (int j = 0; j < 8; j++)
            #pragma unroll
            for (int q = 0; q < 4; q++) d[mt][j][q] = 0.f;

    stageW(0);
    for (int s = 0; s < 27; s++) {
        if (s + 1 < 27) {
            stageW(s + 1);
            asm volatile("cp.async.wait_group 1;" ::: "memory");
        } else {
            asm volatile("cp.async.wait_group 0;" ::: "memory");
        }
        __syncthreads();
        const int tap = s / 3;
        const int dy = tap / 3, dx = tap - 3 * (tap / 3);
        int brow[8];
        #pragma unroll
        for (int j = 0; j < 8; j++) {
            int px = pxg + j * 8 + (lane >> 2);
            brow[j] = (((px >> 5) + dy) * 34 + (px & 31) + dx) * ICS + (lane & 3) * 2;
        }
        const __nv_bfloat16* wb = wt + (s & 1) * WTE;
        #pragma unroll
        for (int kc = 0; kc < 8; kc++) {
            const int kb = kc * 16;
            uint32_t a[2][4];
            #pragma unroll
            for (int mt = 0; mt < 2; mt++) {
                const __nv_bfloat16* ap =
                    wb + (ocg + mt * 16 + (lane >> 2)) * WST + kb + (lane & 3) * 2;
                a[mt][0] = *reinterpret_cast<const uint32_t*>(ap);
                a[mt][1] = *reinterpret_cast<const uint32_t*>(ap + 8 * WST);
                a[mt][2] = *reinterpret_cast<const uint32_t*>(ap + 8);
                a[mt][3] = *reinterpret_cast<const uint32_t*>(ap + 8 * WST + 8);
            }
            #pragma unroll
            for (int j = 0; j < 8; j++) {
                const __nv_bfloat16* bp = slab + brow[j] + kb;
                uint32_t b0 = *reinterpret_cast<const uint32_t*>(bp);
                uint32_t b1 = *reinterpret_cast<const uint32_t*>(bp + 8);
                #pragma unroll
                for (int mt = 0; mt < 2; mt++) {
                    asm volatile(
                        "mma.sync.aligned.m16n8k16.row.col.f32.bf16.bf16.f32 "
                        "{%0,%1,%2,%3}, {%4,%5,%6,%7}, {%8,%9}, {%0,%1,%2,%3};"
                        : "+f"(d[mt][j][0]), "+f"(d[mt][j][1]),
                          "+f"(d[mt][j][2]), "+f"(d[mt][j][3])
                        : "r"(a[mt][0]), "r"(a[mt][1]), "r"(a[mt][2]),
                          "r"(a[mt][3]), "r"(b0), "r"(b1));
                }
            }
        }
        __syncthreads();
    }

    // epilogue 1: store y
    float* yb = y + (size_t)img * CC_ * HW + r0 * 32;
    #pragma unroll
    for (int mt = 0; mt < 2; mt++) {
        int m = ocg + mt * 16 + (lane >> 2);
        #pragma unroll
        for (int j = 0; j < 8; j++) {
            int n = pxg + j * 8 + (lane & 3) * 2;
            *reinterpret_cast<float2*>(&yb[m * HW + n]) =
                make_float2(d[mt][j][0], d[mt][j][1]);
            *reinterpret_cast<float2*>(&yb[(m + 8) * HW + n]) =
                make_float2(d[mt][j][2], d[mt][j][3]);
        }
    }

    // epilogue 2: fused stats. Per-thread -> quad shfl -> smem -> fp64 atomic.
    float rs[4], rq[4];
    #pragma unroll
    for (int h = 0; h < 4; h++) { rs[h] = 0.f; rq[h] = 0.f; }
    #pragma unroll
    for (int mt = 0; mt < 2; mt++)
        #pragma unroll
        for (int j = 0; j < 8; j++) {
            float a0 = d[mt][j][0], a1 = d[mt][j][1];
            float a2 = d[mt][j][2], a3 = d[mt][j][3];
            rs[mt * 2 + 0] += a0 + a1;
            rq[mt * 2 + 0] += a0 * a0 + a1 * a1;
            rs[mt * 2 + 1] += a2 + a3;
            rq[mt * 2 + 1] += a2 * a2 + a3 * a3;
        }
    #pragma unroll
    for (int h = 0; h < 4; h++) {
        rs[h] += __shfl_xor_sync(~0u, rs[h], 1);
        rs[h] += __shfl_xor_sync(~0u, rs[h], 2);
        rq[h] += __shfl_xor_sync(~0u, rq[h], 1);
        rq[h] += __shfl_xor_sync(~0u, rq[h], 2);
    }
    __syncthreads();
    float* sred = reinterpret_cast<float*>(sm);    // 1024 floats (reuse slab)
    if ((lane & 3) == 0) {
        int r = lane >> 2, g = wid >> 2;
        #pragma unroll
        for (int h = 0; h < 4; h++) {
            int oc = ocg + (h >> 1) * 16 + (h & 1) * 8 + r;
            sred[oc * 4 + g] = rs[h];
            sred[512 + oc * 4 + g] = rq[h];
        }
    }
    __syncthreads();
    if (tid < 256) {
        int oc = tid >> 1;
        const float* p = sred + ((tid & 1) ? 512 : 0) + oc * 4;
        double v = (double)p[0] + (double)p[1] + (double)p[2] + (double)p[3];
        atomicAdd((tid & 1) ? &g_sumsq[oc] : &g_sums[oc], v);
    }
}

// ============================================================================
// EXACT direct conv (L1 only) — unchanged.
// ============================================================================
__global__ __launch_bounds__(256, 1)
void conv_x(const float* __restrict__ x, const float* __restrict__ w,
            float* __restrict__ y) {
    __shared__ __align__(16) float in_s[8][10][36];
    __shared__ __align__(16) float w_s[72][64];

    const int tid = threadIdx.x;
    const int img = blockIdx.y;
    const int hbase = ((blockIdx.x >> 1) & 3) * 8;
    const int co_base = (blockIdx.x & 1) * 64;
    const float* xb = x + (size_t)img * CC_ * HW;
    float* yb = y + ((size_t)img * CC_ + co_base) * HW;

    const int oc_g = (tid & 7) * 8;
    const int pg = tid >> 3;
    const int cb = (pg & 7) * 4;
    const int rp = pg >> 3;
    const unsigned long long M1 = dup2(-1.0f);

    unsigned long long hi[2][4][4], lo[2][4][4], ch[2][4][4];
    #pragma unroll
    for (int r = 0; r < 2; r++)
        #pragma unroll
        for (int p = 0; p < 4; p++)
            #pragma unroll
            for (int q = 0; q < 4; q++) { hi[r][p][q]=0ull; lo[r][p][q]=0ull; ch[r][p][q]=0ull; }

    for (int ci0 = 0; ci0 < CC_; ci0 += 8) {
        for (int i = tid; i < 8 * 10 * 34; i += 256) {
            int cch = i / 340;
            int rem = i - cch * 340;
            int r = rem / 34;
            int col = rem - r * 34;
            int gr = hbase + r - 1;
            int gc = col - 1;
            float v = 0.f;
            if ((unsigned)gr < 32u && (unsigned)gc < 32u)
                v = xb[(ci0 + cch) * HW + gr * 32 + gc];
            in_s[cch][r][col] = v;
        }
        for (int i = tid; i < 8 * 9 * 64; i += 256) {
            int oc = i / 72;
            int j = i - oc * 72;
            w_s[j][oc] = w[(co_base + oc) * (CC_ * 9) + ci0 * 9 + j];
        }
        __syncthreads();

        #pragma unroll 2
        for (int cch = 0; cch < 8; cch++) {
            #pragma unroll
            for (int dy = 0; dy < 3; dy++) {
                unsigned long long a0[6], a1[6];
                #pragma unroll
                for (int j = 0; j < 6; j++) {
                    a0[j] = dup2(in_s[cch][rp + dy][cb + j]);
                    a1[j] = dup2(in_s[cch][rp + 4 + dy][cb + j]);
                }
                #pragma unroll
                for (int dx = 0; dx < 3; dx++) {
                    const ulonglong2* wp = reinterpret_cast<const ulonglong2*>(
                        &w_s[cch * 9 + dy * 3 + dx][oc_g]);
                    ulonglong2 wv0 = wp[0];
                    ulonglong2 wv1 = wp[1];
                    unsigned long long wq[4] = {wv0.x, wv0.y, wv1.x, wv1.y};
                    #pragma unroll
                    for (int p = 0; p < 4; p++) {
                        #pragma unroll
                        for (int q = 0; q < 4; q++) {
                            fma2(ch[0][p][q], a0[p + dx], wq[q]);
                            fma2(ch[1][p][q], a1[p + dx], wq[q]);
                        }
                    }
                }
            }
        }
        __syncthreads();

        if ((ci0 >> 3) & 1) {
            #pragma unroll
            for (int r = 0; r < 2; r++)
                #pragma unroll
                for (int p = 0; p < 4; p++)
                    #pragma unroll
                    for (int q = 0; q < 4; q++) {
                        unsigned long long c = ch[r][p][q];
                        unsigned long long s = add2(hi[r][p][q], c);
                        unsigned long long zz = add2(s, mul2(hi[r][p][q], M1));
                        unsigned long long e = add2(c, mul2(zz, M1));
                        lo[r][p][q] = add2(lo[r][p][q], e);
                        hi[r][p][q] = s;
                        ch[r][p][q] = 0ull;
                    }
        }
    }

    #pragma unroll
    for (int r = 0; r < 2; r++) {
        int h = hbase + rp + 4 * r;
        #pragma unroll
        for (int q = 0; q < 4; q++) {
            float2 t0 = unp(add2(hi[r][0][q], lo[r][0][q]));
            float2 t1 = unp(add2(hi[r][1][q], lo[r][1][q]));
            float2 t2 = unp(add2(hi[r][2][q], lo[r][2][q]));
            float2 t3 = unp(add2(hi[r][3][q], lo[r][3][q]));
            *reinterpret_cast<float4*>(&yb[(oc_g + 2*q) * HW + h*32 + cb]) =
                make_float4(t0.x, t1.x, t2.x, t3.x);
            *reinterpret_cast<float4*>(&yb[(oc_g + 2*q + 1) * HW + h*32 + cb]) =
                make_float4(t0.y, t1.y, t2.y, t3.y);
        }
    }
}

// ============================================================================
// helpers
// ============================================================================
__global__ void zero_feat_k() {
    int t = threadIdx.x;
    for (int i = t; i < BB * CC_; i += 256) g_feat[i] = 0.f;
}
__global__ void zero_stats_k() {
    int t = threadIdx.x;
    if (t < CC_) { g_sums[t] = 0.0; g_sumsq[t] = 0.0; }
}
__global__ void stats_k(const float* __restrict__ y) {   // L1 only
    __shared__ double s1[256], s2[256];
    const int c = blockIdx.x;
    const int g = blockIdx.y;
    const int tid = threadIdx.x;
    double S = 0.0, SS = 0.0;
    const float* base = y + ((size_t)(g * 32) * CC_ + c) * HW;
    for (int i0 = tid; i0 < 32 * HW; i0 += 256 * 8) {
        float s = 0.f, ss = 0.f;
        #pragma unroll
        for (int k = 0; k < 8; k++) {
            int i = i0 + k * 256;
            float v = base[(size_t)(i >> 10) * CC_ * HW + (i & 1023)];
            s += v; ss += v * v;
        }
        S += (double)s; SS += (double)ss;
    }
    s1[tid] = S; s2[tid] = SS;
    __syncthreads();
    for (int o = 128; o > 0; o >>= 1) {
        if (tid < o) { s1[tid] += s1[tid + o]; s2[tid] += s2[tid + o]; }
        __syncthreads();
    }
    if (tid == 0) {
        atomicAdd(&g_sums[c], s1[0]);
        atomicAdd(&g_sumsq[c], s2[0]);
    }
}
__global__ void finalize_k(int slot) {
    int c = threadIdx.x;
    if (c >= CC_) return;
    const double invN = 1.0 / (double)(TT * BB * HW);
    double mean = g_sums[c] * invN;
    double var = g_sumsq[c] * invN - mean * mean;
    g_meanA[slot][c] = (float)mean;
    g_rstdA[slot][c] = (float)(1.0 / sqrt(var + 1e-5));
}

// member BN + LIF (binary cascade with synthetic noise); spikes out as bf16.
template <bool POOL>
__global__ void lif_k(const float* __restrict__ y, __nv_bfloat16* __restrict__ spk,
                      const float* __restrict__ bnw, const float* __restrict__ bnb,
                      int slot, unsigned seed, float sgnsigma) {
    const int tid = threadIdx.x;
    const int idx = blockIdx.x * 256 + tid;
    const int c = (idx >> 10) & (CC_ - 1);
    const float mean = g_meanA[slot][c];
    const float rs = g_rstdA[slot][c];
    const float wv = bnw[c];
    const float bv = bnb[c];

    float mem = 0.f, s = 0.f, acc = 0.f;
    #pragma unroll
    for (int t = 0; t < TT; t++) {
        float xv = y[(size_t)t * PLANE + idx];
        xv += gnoise((unsigned)(idx + t * PLANE), seed) * sgnsigma;
        float xn = __fmul_rn(__fsub_rn(xv, mean), rs);
        float v  = __fadd_rn(__fmul_rn(xn, wv), bv);
        mem = fmaf(mem, 0.25f * (1.f - s), v);
        s = (mem > 0.5f) ? 1.f : 0.f;
        if (POOL) acc += s;
        else spk[(size_t)t * PLANE + idx] = __float2bfloat16_rn(s);
    }
    if (POOL) {
        __shared__ float red[256];
        red[tid] = acc;
        __syncthreads();
        for (int o = 128; o > 0; o >>= 1) {
            if (tid < o) red[tid] += red[tid + o];
            __syncthreads();
        }
        if (tid == 0) atomicAdd(&g_feat[idx >> 10], red[0]);
    }
}

__global__ void fc_k(const float* __restrict__ fcw, const float* __restrict__ fcb,
                     float* __restrict__ out) {
    int t = threadIdx.x;
    if (t >= BB * 10) return;
    int b = t / 10, k = t - b * 10;
    const float sc = 1.f / (float)(KMEM * TT * HW);
    float s = 0.f;
    for (int c = 0; c < CC_; c++)
        s = fmaf(g_feat[b * CC_ + c] * sc, fcw[k * CC_ + c], s);
    out[t] = s + fcb[k];
}

// ============================================================================
// launch
// ============================================================================
extern "C" void kernel_launch(void* const* d_in, const int* in_sizes, int n_in,
                              void* d_out, int out_size) {
    const float* inp = (const float*)d_in[0];
    const float* w1  = (const float*)d_in[1];
    const float* w2  = (const float*)d_in[2];
    const float* w3  = (const float*)d_in[3];
    const float* bw1 = (const float*)d_in[4];
    const float* bb1 = (const float*)d_in[5];
    const float* bw2 = (const float*)d_in[6];
    const float* bb2 = (const float*)d_in[7];
    const float* bw3 = (const float*)d_in[8];
    const float* bb3 = (const float*)d_in[9];
    const float* fcw = (const float*)d_in[10];
    const float* fcb = (const float*)d_in[11];
    float* out = (float*)d_out;

    float *bufL1, *bufC;
    __nv_bfloat16 *bufS, *wsp;
    cudaGetSymbolAddress((void**)&bufL1, g_bufL1);
    cudaGetSymbolAddress((void**)&bufS, g_bufS);
    cudaGetSymbolAddress((void**)&bufC, g_bufC);
    cudaGetSymbolAddress((void**)&wsp, g_wsp);

    cudaFuncSetAttribute(conv_t, cudaFuncAttributeMaxDynamicSharedMemorySize,
                         CONVT_SMEM);

    const dim3 cgrid(8, IMG);
    const dim3 tgrid(4, IMG);
    const dim3 sgrid(CC_, 8);
    const int lgrid = PLANE / 256;

    zero_feat_k<<<1, 256>>>();
    prep_w<<<(2 * 9 * CC_ * CC_ + 255) / 256, 256>>>(w2, w3);

    conv_x<<<cgrid, 256>>>(inp, w1, bufL1);
    zero_stats_k<<<1, 256>>>();
    stats_k<<<sgrid, 256>>>(bufL1);
    finalize_k<<<1, 128>>>(1);

    for (int m = 0; m < KMEM; m++) {
        unsigned pair = (unsigned)(m >> 1);
        float sg = (m & 1) ? -SIGMA : SIGMA;

        lif_k<false><<<lgrid, 256>>>(bufL1, bufS, bw1, bb1, 1, pair * 3u + 0u, sg);

        zero_stats_k<<<1, 256>>>();
        conv_t<<<tgrid, 512, CONVT_SMEM>>>(bufS, wsp, bufC);
        finalize_k<<<1, 128>>>(0);
        lif_k<false><<<lgrid, 256>>>(bufC, bufS, bw2, bb2, 0, pair * 3u + 1u, sg);

        zero_stats_k<<<1, 256>>>();
        conv_t<<<tgrid, 512, CONVT_SMEM>>>(bufS, wsp + (size_t)27 * WTE, bufC);
        finalize_k<<<1, 128>>>(0);
        lif_k<true><<<lgrid, 256>>>(bufC, nullptr, bw3, bb3, 0, pair * 3u + 2u, sg);
    }

    fc_k<<<1, 320>>>(fcw, fcb, out);
}

// round 16
// speedup vs baseline: 1.3244x; 1.3244x over previous
#include <cuda_runtime.h>
#include <cuda_bf16.h>
#include <cstdint>

#define TT 8
#define BB 32
#define CC_ 128
#define HW 1024
#define IMG 256
#define PLANE (BB*CC_*HW)
#define TOT (TT*PLANE)

#define KMEM 16
#define SIGMA 5.0e-6f

#define ICS 136
#define WST 132
#define WTE (128*WST)                    // 16896 elems = 2112 float4
#define SLAB_E (10*34*ICS)
#define CONVT_SMEM ((SLAB_E + 2*WTE)*2)  // 160064 B

__device__ float  g_bufL1[TOT];
__device__ __nv_bfloat16 g_bufS[(size_t)KMEM*TOT];
__device__ float  g_bufC[(size_t)KMEM*TOT];
__device__ __nv_bfloat16 g_wsp[54*WTE];
__device__ double g_sL1[CC_], g_qL1[CC_];
__device__ float  g_meanL1[CC_], g_rstdL1[CC_];
__device__ double g_sumsB[KMEM*CC_], g_sumsqB[KMEM*CC_];
__device__ float  g_meanB[KMEM*CC_], g_rstdB[KMEM*CC_];
__device__ float  g_feat[BB*CC_];

// ---- packed f32x2 helpers (L1 exact conv) ----
__device__ __forceinline__ unsigned long long dup2(float v) {
    unsigned long long r; unsigned u = __float_as_uint(v);
    asm("mov.b64 %0, {%1, %1};" : "=l"(r) : "r"(u));
    return r;
}
__device__ __forceinline__ void fma2(unsigned long long& d,
                                     unsigned long long a, unsigned long long b) {
    asm("fma.rn.f32x2 %0, %1, %2, %0;" : "+l"(d) : "l"(a), "l"(b));
}
__device__ __forceinline__ unsigned long long add2(unsigned long long a,
                                                   unsigned long long b) {
    unsigned long long r;
    asm("add.rn.f32x2 %0, %1, %2;" : "=l"(r) : "l"(a), "l"(b));
    return r;
}
__device__ __forceinline__ unsigned long long mul2(unsigned long long a,
                                                   unsigned long long b) {
    unsigned long long r;
    asm("mul.rn.f32x2 %0, %1, %2;" : "=l"(r) : "l"(a), "l"(b));
    return r;
}
__device__ __forceinline__ float2 unp(unsigned long long v) {
    unsigned lo, hi;
    asm("mov.b64 {%0, %1}, %2;" : "=r"(lo), "=r"(hi) : "l"(v));
    return make_float2(__uint_as_float(lo), __uint_as_float(hi));
}

__device__ __forceinline__ float gnoise(unsigned gid, unsigned seed) {
    unsigned h = gid ^ (seed * 0x9E3779B9u);
    h ^= h >> 16; h *= 0x7feb352du;
    h ^= h >> 15; h *= 0x846ca68bu;
    h ^= h >> 16;
    int s = (int)((h & 255u) + ((h >> 8) & 255u) + ((h >> 16) & 255u) +
                  ((h >> 24) & 255u)) - 510;
    return (float)s * (1.0f / 147.8f);
}

// ============================================================================
// Weight prep: 3-way bf16 split (exact products vs binary spikes).
// ============================================================================
__global__ void prep_w(const float* __restrict__ w2, const float* __restrict__ w3) {
    int idx = blockIdx.x * 256 + threadIdx.x;
    if (idx >= 2 * 9 * CC_ * CC_) return;
    int ic = idx & 127;
    int oc = (idx >> 7) & 127;
    int rest = idx >> 14;
    int tap = rest % 9, layer = rest / 9;
    const float* w = layer ? w3 : w2;
    float v = w[(oc * CC_ + ic) * 9 + tap];
    __nv_bfloat16 b1 = __float2bfloat16_rn(v);
    float r1 = v - __bfloat162float(b1);
    __nv_bfloat16 b2 = __float2bfloat16_rn(r1);
    __nv_bfloat16 b3 = __float2bfloat16_rn(r1 - __bfloat162float(b2));
    size_t tb = ((size_t)layer * 27 + tap * 3) * WTE + (size_t)oc * WST;
    g_wsp[tb + ic] = b1;
    g_wsp[tb + WTE + ic] = b2;
    g_wsp[tb + 2 * WTE + ic] = b3;
    if (ic < 4) {
        __nv_bfloat16 z = __float2bfloat16_rn(0.f);
        g_wsp[tb + 128 + ic] = z;
        g_wsp[tb + WTE + 128 + ic] = z;
        g_wsp[tb + 2 * WTE + 128 + ic] = z;
    }
}

// ============================================================================
// Tensor-core member conv + fused stats. grid (4, IMG, KMEM).
// Register-prefetch double-buffered weight staging (LDG overlapped with MMA).
// ============================================================================
__global__ __launch_bounds__(512, 1)
void conv_t(const __nv_bfloat16* __restrict__ spkBase,
            const __nv_bfloat16* __restrict__ wsp, float* __restrict__ yBase) {
    extern __shared__ __nv_bfloat16 sm[];
    __nv_bfloat16* slab = sm;
    __nv_bfloat16* wt = sm + SLAB_E;

    const int tid = threadIdx.x;
    const int img = blockIdx.y;
    const int mem = blockIdx.z;
    const int r0 = blockIdx.x * 8;
    const int wid = tid >> 5, lane = tid & 31;
    const int ocg = (wid & 3) * 32;
    const int pxg = (wid >> 2) * 64;
    const __nv_bfloat16 z = __float2bfloat16_rn(0.f);

    const __nv_bfloat16* sb = spkBase + (size_t)mem * TOT + (size_t)img * CC_ * HW;
    for (int job = tid; job < 128 * 10; job += 512) {
        int ic = job / 10, srow = job - 10 * ic;
        int gr = r0 + srow - 1;
        __nv_bfloat16* drow = slab + (srow * 34) * ICS + ic;
        if ((unsigned)gr < 32u) {
            const uint4* src = reinterpret_cast<const uint4*>(sb + ic * HW + gr * 32);
            drow[0] = z;
            #pragma unroll
            for (int c8 = 0; c8 < 4; c8++) {
                uint4 u = src[c8];
                const __nv_bfloat16* e = reinterpret_cast<const __nv_bfloat16*>(&u);
                #pragma unroll
                for (int k = 0; k < 8; k++) drow[(c8 * 8 + k + 1) * ICS] = e[k];
            }
            drow[33 * ICS] = z;
        } else {
            #pragma unroll
            for (int c = 0; c < 34; c++) drow[c * ICS] = z;
        }
    }

    float4 pf[5];
    auto ldW = [&](int s) {
        const float4* src = reinterpret_cast<const float4*>(wsp + (size_t)s * WTE);
        #pragma unroll
        for (int k = 0; k < 5; k++) {
            int i = tid + k * 512;
            if (i < 2112) pf[k] = src[i];
        }
    };
    auto stW = [&](int s) {
        float4* dst = reinterpret_cast<float4*>(wt + (s & 1) * WTE);
        #pragma unroll
        for (int k = 0; k < 5; k++) {
            int i = tid + k * 512;
            if (i < 2112) dst[i] = pf[k];
        }
    };

    float d[2][8][4];
    #pragma unroll
    for (int mt = 0; mt < 2; mt++)
        #pragma unroll
        for (int j = 0; j < 8; j++)
            #pragma unroll
            for (int q = 0; q < 4; q++) d[mt][j][q] = 0.f;

    ldW(0); stW(0);
    __syncthreads();
    for (int s = 0; s < 27; s++) {
        if (s + 1 < 27) ldW(s + 1);          // LDG latency hidden behind MMA
        const int tap = s / 3;
        const int dy = tap / 3, dx = tap - 3 * (tap / 3);
        int brow[8];
        #pragma unroll
        for (int j = 0; j < 8; j++) {
            int px = pxg + j * 8 + (lane >> 2);
            brow[j] = (((px >> 5) + dy) * 34 + (px & 31) + dx) * ICS + (lane & 3) * 2;
        }
        const __nv_bfloat16* wb = wt + (s & 1) * WTE;
        #pragma unroll
        for (int kc = 0; kc < 8; kc++) {
            const int kb = kc * 16;
            uint32_t a[2][4];
            #pragma unroll
            for (int mt = 0; mt < 2; mt++) {
                const __nv_bfloat16* ap =
                    wb + (ocg + mt * 16 + (lane >> 2)) * WST + kb + (lane & 3) * 2;
                a[mt][0] = *reinterpret_cast<const uint32_t*>(ap);
                a[mt][1] = *reinterpret_cast<const uint32_t*>(ap + 8 * WST);
                a[mt][2] = *reinterpret_cast<const uint32_t*>(ap + 8);
                a[mt][3] = *reinterpret_cast<const uint32_t*>(ap + 8 * WST + 8);
            }
            #pragma unroll
            for (int j = 0; j < 8; j++) {
                const __nv_bfloat16* bp = slab + brow[j] + kb;
                uint32_t b0 = *reinterpret_cast<const uint32_t*>(bp);
                uint32_t b1 = *reinterpret_cast<const uint32_t*>(bp + 8);
                #pragma unroll
                for (int mt = 0; mt < 2; mt++) {
                    asm volatile(
                        "mma.sync.aligned.m16n8k16.row.col.f32.bf16.bf16.f32 "
                        "{%0,%1,%2,%3}, {%4,%5,%6,%7}, {%8,%9}, {%0,%1,%2,%3};"
                        : "+f"(d[mt][j][0]), "+f"(d[mt][j][1]),
                          "+f"(d[mt][j][2]), "+f"(d[mt][j][3])
                        : "r"(a[mt][0]), "r"(a[mt][1]), "r"(a[mt][2]),
                          "r"(a[mt][3]), "r"(b0), "r"(b1));
                }
            }
        }
        __syncthreads();
        if (s + 1 < 27) {
            stW(s + 1);
            __syncthreads();
        }
    }

    float* yb = yBase + (size_t)mem * TOT + (size_t)img * CC_ * HW + r0 * 32;
    #pragma unroll
    for (int mt = 0; mt < 2; mt++) {
        int m = ocg + mt * 16 + (lane >> 2);
        #pragma unroll
        for (int j = 0; j < 8; j++) {
            int n = pxg + j * 8 + (lane & 3) * 2;
            *reinterpret_cast<float2*>(&yb[m * HW + n]) =
                make_float2(d[mt][j][0], d[mt][j][1]);
            *reinterpret_cast<float2*>(&yb[(m + 8) * HW + n]) =
                make_float2(d[mt][j][2], d[mt][j][3]);
        }
    }

    // fused stats: thread -> quad shfl -> smem -> fp64 atomics (per member)
    float rs[4], rq[4];
    #pragma unroll
    for (int h = 0; h < 4; h++) { rs[h] = 0.f; rq[h] = 0.f; }
    #pragma unroll
    for (int mt = 0; mt < 2; mt++)
        #pragma unroll
        for (int j = 0; j < 8; j++) {
            float a0 = d[mt][j][0], a1 = d[mt][j][1];
            float a2 = d[mt][j][2], a3 = d[mt][j][3];
            rs[mt * 2 + 0] += a0 + a1;
            rq[mt * 2 + 0] += a0 * a0 + a1 * a1;
            rs[mt * 2 + 1] += a2 + a3;
            rq[mt * 2 + 1] += a2 * a2 + a3 * a3;
        }
    #pragma unroll
    for (int h = 0; h < 4; h++) {
        rs[h] += __shfl_xor_sync(~0u, rs[h], 1);
        rs[h] += __shfl_xor_sync(~0u, rs[h], 2);
        rq[h] += __shfl_xor_sync(~0u, rq[h], 1);
        rq[h] += __shfl_xor_sync(~0u, rq[h], 2);
    }
    __syncthreads();
    float* sred = reinterpret_cast<float*>(sm);
    if ((lane & 3) == 0) {
        int r = lane >> 2, g = wid >> 2;
        #pragma unroll
        for (int h = 0; h < 4; h++) {
            int oc = ocg + (h >> 1) * 16 + (h & 1) * 8 + r;
            sred[oc * 4 + g] = rs[h];
            sred[512 + oc * 4 + g] = rq[h];
        }
    }
    __syncthreads();
    if (tid < 256) {
        int oc = tid >> 1;
        const float* p = sred + ((tid & 1) ? 512 : 0) + oc * 4;
        double v = (double)p[0] + (double)p[1] + (double)p[2] + (double)p[3];
        atomicAdd((tid & 1) ? &g_sumsqB[mem * CC_ + oc] : &g_sumsB[mem * CC_ + oc], v);
    }
}

// ============================================================================
// EXACT direct conv (L1 only) — unchanged.
// ============================================================================
__global__ __launch_bounds__(256, 1)
void conv_x(const float* __restrict__ x, const float* __restrict__ w,
            float* __restrict__ y) {
    __shared__ __align__(16) float in_s[8][10][36];
    __shared__ __align__(16) float w_s[72][64];

    const int tid = threadIdx.x;
    const int img = blockIdx.y;
    const int hbase = ((blockIdx.x >> 1) & 3) * 8;
    const int co_base = (blockIdx.x & 1) * 64;
    const float* xb = x + (size_t)img * CC_ * HW;
    float* yb = y + ((size_t)img * CC_ + co_base) * HW;

    const int oc_g = (tid & 7) * 8;
    const int pg = tid >> 3;
    const int cb = (pg & 7) * 4;
    const int rp = pg >> 3;
    const unsigned long long M1 = dup2(-1.0f);

    unsigned long long hi[2][4][4], lo[2][4][4], ch[2][4][4];
    #pragma unroll
    for (int r = 0; r < 2; r++)
        #pragma unroll
        for (int p = 0; p < 4; p++)
            #pragma unroll
            for (int q = 0; q < 4; q++) { hi[r][p][q]=0ull; lo[r][p][q]=0ull; ch[r][p][q]=0ull; }

    for (int ci0 = 0; ci0 < CC_; ci0 += 8) {
        for (int i = tid; i < 8 * 10 * 34; i += 256) {
            int cch = i / 340;
            int rem = i - cch * 340;
            int r = rem / 34;
            int col = rem - r * 34;
            int gr = hbase + r - 1;
            int gc = col - 1;
            float v = 0.f;
            if ((unsigned)gr < 32u && (unsigned)gc < 32u)
                v = xb[(ci0 + cch) * HW + gr * 32 + gc];
            in_s[cch][r][col] = v;
        }
        for (int i = tid; i < 8 * 9 * 64; i += 256) {
            int oc = i / 72;
            int j = i - oc * 72;
            w_s[j][oc] = w[(co_base + oc) * (CC_ * 9) + ci0 * 9 + j];
        }
        __syncthreads();

        #pragma unroll 2
        for (int cch = 0; cch < 8; cch++) {
            #pragma unroll
            for (int dy = 0; dy < 3; dy++) {
                unsigned long long a0[6], a1[6];
                #pragma unroll
                for (int j = 0; j < 6; j++) {
                    a0[j] = dup2(in_s[cch][rp + dy][cb + j]);
                    a1[j] = dup2(in_s[cch][rp + 4 + dy][cb + j]);
                }
                #pragma unroll
                for (int dx = 0; dx < 3; dx++) {
                    const ulonglong2* wp = reinterpret_cast<const ulonglong2*>(
                        &w_s[cch * 9 + dy * 3 + dx][oc_g]);
                    ulonglong2 wv0 = wp[0];
                    ulonglong2 wv1 = wp[1];
                    unsigned long long wq[4] = {wv0.x, wv0.y, wv1.x, wv1.y};
                    #pragma unroll
                    for (int p = 0; p < 4; p++) {
                        #pragma unroll
                        for (int q = 0; q < 4; q++) {
                            fma2(ch[0][p][q], a0[p + dx], wq[q]);
                            fma2(ch[1][p][q], a1[p + dx], wq[q]);
                        }
                    }
                }
            }
        }
        __syncthreads();

        if ((ci0 >> 3) & 1) {
            #pragma unroll
            for (int r = 0; r < 2; r++)
                #pragma unroll
                for (int p = 0; p < 4; p++)
                    #pragma unroll
                    for (int q = 0; q < 4; q++) {
                        unsigned long long c = ch[r][p][q];
                        unsigned long long s = add2(hi[r][p][q], c);
                        unsigned long long zz = add2(s, mul2(hi[r][p][q], M1));
                        unsigned long long e = add2(c, mul2(zz, M1));
                        lo[r][p][q] = add2(lo[r][p][q], e);
                        hi[r][p][q] = s;
                        ch[r][p][q] = 0ull;
                    }
        }
    }

    #pragma unroll
    for (int r = 0; r < 2; r++) {
        int h = hbase + rp + 4 * r;
        #pragma unroll
        for (int q = 0; q < 4; q++) {
            float2 t0 = unp(add2(hi[r][0][q], lo[r][0][q]));
            float2 t1 = unp(add2(hi[r][1][q], lo[r][1][q]));
            float2 t2 = unp(add2(hi[r][2][q], lo[r][2][q]));
            float2 t3 = unp(add2(hi[r][3][q], lo[r][3][q]));
            *reinterpret_cast<float4*>(&yb[(oc_g + 2*q) * HW + h*32 + cb]) =
                make_float4(t0.x, t1.x, t2.x, t3.x);
            *reinterpret_cast<float4*>(&yb[(oc_g + 2*q + 1) * HW + h*32 + cb]) =
                make_float4(t0.y, t1.y, t2.y, t3.y);
        }
    }
}

// ============================================================================
// helpers
// ============================================================================
__global__ void zero_all_k() {
    int t = blockIdx.x * 256 + threadIdx.x;
    if (t < BB * CC_) g_feat[t] = 0.f;
    if (t < CC_) { g_sL1[t] = 0.0; g_qL1[t] = 0.0; }
}
__global__ void zeroB_k() {
    int t = blockIdx.x * 256 + threadIdx.x;
    if (t < KMEM * CC_) { g_sumsB[t] = 0.0; g_sumsqB[t] = 0.0; }
}
__global__ void statsL1_k(const float* __restrict__ y) {
    __shared__ double s1[256], s2[256];
    const int c = blockIdx.x;
    const int g = blockIdx.y;
    const int tid = threadIdx.x;
    double S = 0.0, SS = 0.0;
    const float* base = y + ((size_t)(g * 32) * CC_ + c) * HW;
    for (int i0 = tid; i0 < 32 * HW; i0 += 256 * 8) {
        float s = 0.f, ss = 0.f;
        #pragma unroll
        for (int k = 0; k < 8; k++) {
            int i = i0 + k * 256;
            float v = base[(size_t)(i >> 10) * CC_ * HW + (i & 1023)];
            s += v; ss += v * v;
        }
        S += (double)s; SS += (double)ss;
    }
    s1[tid] = S; s2[tid] = SS;
    __syncthreads();
    for (int o = 128; o > 0; o >>= 1) {
        if (tid < o) { s1[tid] += s1[tid + o]; s2[tid] += s2[tid + o]; }
        __syncthreads();
    }
    if (tid == 0) { atomicAdd(&g_sL1[c], s1[0]); atomicAdd(&g_qL1[c], s2[0]); }
}
__global__ void finalizeL1_k() {
    int c = threadIdx.x;
    if (c >= CC_) return;
    const double invN = 1.0 / (double)(TT * BB * HW);
    double mean = g_sL1[c] * invN;
    double var = g_qL1[c] * invN - mean * mean;
    g_meanL1[c] = (float)mean;
    g_rstdL1[c] = (float)(1.0 / sqrt(var + 1e-5));
}
__global__ void finalizeB_k() {
    int i = blockIdx.x * 128 + threadIdx.x;
    if (i >= KMEM * CC_) return;
    const double invN = 1.0 / (double)(TT * BB * HW);
    double mean = g_sumsB[i] * invN;
    double var = g_sumsqB[i] * invN - mean * mean;
    g_meanB[i] = (float)mean;
    g_rstdB[i] = (float)(1.0 / sqrt(var + 1e-5));
}

// batched member BN + LIF. grid (PLANE/256, KMEM). ystride/mstride select
// shared-L1 vs per-member sources. Numerics identical to passing config.
template <bool POOL>
__global__ void lifB_k(const float* __restrict__ y, size_t ystride,
                       __nv_bfloat16* __restrict__ spk,
                       const float* __restrict__ bnw, const float* __restrict__ bnb,
                       const float* __restrict__ meanp, const float* __restrict__ rstdp,
                       int mstride, unsigned st) {
    const int tid = threadIdx.x;
    const int idx = blockIdx.x * 256 + tid;
    const int m = blockIdx.y;
    const int c = (idx >> 10) & (CC_ - 1);
    const unsigned seed = (unsigned)(m >> 1) * 3u + st;
    const float sg = (m & 1) ? -SIGMA : SIGMA;
    const float mean = meanp[m * mstride + c];
    const float rs = rstdp[m * mstride + c];
    const float wv = bnw[c];
    const float bv = bnb[c];
    const float* yb = y + (size_t)m * ystride;

    float memv = 0.f, s = 0.f, acc = 0.f;
    #pragma unroll
    for (int t = 0; t < TT; t++) {
        float xv = yb[(size_t)t * PLANE + idx];
        xv += gnoise((unsigned)(idx + t * PLANE), seed) * sg;
        float xn = __fmul_rn(__fsub_rn(xv, mean), rs);
        float v  = __fadd_rn(__fmul_rn(xn, wv), bv);
        memv = fmaf(memv, 0.25f * (1.f - s), v);
        s = (memv > 0.5f) ? 1.f : 0.f;
        if (POOL) acc += s;
        else spk[(size_t)m * TOT + (size_t)t * PLANE + idx] = __float2bfloat16_rn(s);
    }
    if (POOL) {
        __shared__ float red[256];
        red[tid] = acc;
        __syncthreads();
        for (int o = 128; o > 0; o >>= 1) {
            if (tid < o) red[tid] += red[tid + o];
            __syncthreads();
        }
        if (tid == 0) atomicAdd(&g_feat[idx >> 10], red[0]);
    }
}

__global__ void fc_k(const float* __restrict__ fcw, const float* __restrict__ fcb,
                     float* __restrict__ out) {
    int t = threadIdx.x;
    if (t >= BB * 10) return;
    int b = t / 10, k = t - b * 10;
    const float sc = 1.f / (float)(KMEM * TT * HW);
    float s = 0.f;
    for (int c = 0; c < CC_; c++)
        s = fmaf(g_feat[b * CC_ + c] * sc, fcw[k * CC_ + c], s);
    out[t] = s + fcb[k];
}

// ============================================================================
// launch
// ============================================================================
extern "C" void kernel_launch(void* const* d_in, const int* in_sizes, int n_in,
                              void* d_out, int out_size) {
    const float* inp = (const float*)d_in[0];
    const float* w1  = (const float*)d_in[1];
    const float* w2  = (const float*)d_in[2];
    const float* w3  = (const float*)d_in[3];
    const float* bw1 = (const float*)d_in[4];
    const float* bb1 = (const float*)d_in[5];
    const float* bw2 = (const float*)d_in[6];
    const float* bb2 = (const float*)d_in[7];
    const float* bw3 = (const float*)d_in[8];
    const float* bb3 = (const float*)d_in[9];
    const float* fcw = (const float*)d_in[10];
    const float* fcb = (const float*)d_in[11];
    float* out = (float*)d_out;

    float *bufL1, *bufC, *meanL1, *rstdL1, *meanB, *rstdB;
    __nv_bfloat16 *bufS, *wsp;
    cudaGetSymbolAddress((void**)&bufL1, g_bufL1);
    cudaGetSymbolAddress((void**)&bufS, g_bufS);
    cudaGetSymbolAddress((void**)&bufC, g_bufC);
    cudaGetSymbolAddress((void**)&wsp, g_wsp);
    cudaGetSymbolAddress((void**)&meanL1, g_meanL1);
    cudaGetSymbolAddress((void**)&rstdL1, g_rstdL1);
    cudaGetSymbolAddress((void**)&meanB, g_meanB);
    cudaGetSymbolAddress((void**)&rstdB, g_rstdB);

    cudaFuncSetAttribute(conv_t, cudaFuncAttributeMaxDynamicSharedMemorySize,
                         CONVT_SMEM);

    const dim3 cgrid(8, IMG);
    const dim3 tgrid(4, IMG, KMEM);
    const dim3 sgrid(CC_, 8);
    const dim3 lgrid(PLANE / 256, KMEM);
    const int zb = (KMEM * CC_ + 255) / 256;

    zero_all_k<<<(BB * CC_ + 255) / 256, 256>>>();
    prep_w<<<(2 * 9 * CC_ * CC_ + 255) / 256, 256>>>(w2, w3);

    // shared L1: exact conv + stats
    conv_x<<<cgrid, 256>>>(inp, w1, bufL1);
    statsL1_k<<<sgrid, 256>>>(bufL1);
    finalizeL1_k<<<1, 128>>>();

    // batched ensemble: L1 lif -> L2 conv/lif -> L3 conv/lif(pool)
    lifB_k<false><<<lgrid, 256>>>(bufL1, 0, bufS, bw1, bb1, meanL1, rstdL1, 0, 0u);

    zeroB_k<<<zb, 256>>>();
    conv_t<<<tgrid, 512, CONVT_SMEM>>>(bufS, wsp, bufC);
    finalizeB_k<<<(KMEM * CC_ + 127) / 128, 128>>>();
    lifB_k<false><<<lgrid, 256>>>(bufC, (size_t)TOT, bufS, bw2, bb2,
                                  meanB, rstdB, CC_, 1u);

    zeroB_k<<<zb, 256>>>();
    conv_t<<<tgrid, 512, CONVT_SMEM>>>(bufS, wsp + (size_t)27 * WTE, bufC);
    finalizeB_k<<<(KMEM * CC_ + 127) / 128, 128>>>();
    lifB_k<true><<<lgrid, 256>>>(bufC, (size_t)TOT, nullptr, bw3, bb3,
                                 meanB, rstdB, CC_, 2u);

    fc_k<<<1, 320>>>(fcw, fcb, out);
}

// round 17
// speedup vs baseline: 1.8171x; 1.3720x over previous
#include <cuda_runtime.h>
#include <cuda_bf16.h>
#include <cuda_fp16.h>
#include <cstdint>

#define TT 8
#define BB 32
#define CC_ 128
#define HW 1024
#define IMG 256
#define PLANE (BB*CC_*HW)
#define TOT (TT*PLANE)

#define KMEM 16
#define SIGMA 5.0e-6f

#define ICS 136
#define WST 136                          // padded: conflict-free A-fragment LDS
#define WTE (128*WST)                    // 17408 elems = 2176 float4
#define NSTG 18                          // 9 taps x 2 fp16 splits
#define SLAB_E (10*34*ICS)
#define CONVT_SMEM ((SLAB_E + 2*WTE)*2)  // 162112 B

__device__ float  g_bufL1[TOT];
__device__ __half g_bufS[(size_t)KMEM*TOT];   // spikes (0/1 exact in fp16)
__device__ float  g_bufC[(size_t)KMEM*TOT];
__device__ __half g_wsp[2*NSTG*WTE];          // [layer][tap*2+split][oc][WST]
__device__ double g_sL1[CC_], g_qL1[CC_];
__device__ float  g_meanL1[CC_], g_rstdL1[CC_];
__device__ double g_sumsB[KMEM*CC_], g_sumsqB[KMEM*CC_];
__device__ float  g_meanB[KMEM*CC_], g_rstdB[KMEM*CC_];
__device__ float  g_feat[BB*CC_];

// ---- packed f32x2 helpers (L1 exact conv) ----
__device__ __forceinline__ unsigned long long dup2(float v) {
    unsigned long long r; unsigned u = __float_as_uint(v);
    asm("mov.b64 %0, {%1, %1};" : "=l"(r) : "r"(u));
    return r;
}
__device__ __forceinline__ void fma2(unsigned long long& d,
                                     unsigned long long a, unsigned long long b) {
    asm("fma.rn.f32x2 %0, %1, %2, %0;" : "+l"(d) : "l"(a), "l"(b));
}
__device__ __forceinline__ unsigned long long add2(unsigned long long a,
                                                   unsigned long long b) {
    unsigned long long r;
    asm("add.rn.f32x2 %0, %1, %2;" : "=l"(r) : "l"(a), "l"(b));
    return r;
}
__device__ __forceinline__ unsigned long long mul2(unsigned long long a,
                                                   unsigned long long b) {
    unsigned long long r;
    asm("mul.rn.f32x2 %0, %1, %2;" : "=l"(r) : "l"(a), "l"(b));
    return r;
}
__device__ __forceinline__ float2 unp(unsigned long long v) {
    unsigned lo, hi;
    asm("mov.b64 {%0, %1}, %2;" : "=r"(lo), "=r"(hi) : "l"(v));
    return make_float2(__uint_as_float(lo), __uint_as_float(hi));
}

__device__ __forceinline__ float gnoise(unsigned gid, unsigned seed) {
    unsigned h = gid ^ (seed * 0x9E3779B9u);
    h ^= h >> 16; h *= 0x7feb352du;
    h ^= h >> 15; h *= 0x846ca68bu;
    h ^= h >> 16;
    int s = (int)((h & 255u) + ((h >> 8) & 255u) + ((h >> 16) & 255u) +
                  ((h >> 24) & 255u)) - 510;
    return (float)s * (1.0f / 147.8f);
}

// ============================================================================
// Weight prep: 2-way fp16 split. Residual <= 2^-25 absolute (subnormal fp16
// second split) => products vs binary spikes exact to ~3e-8.
// ============================================================================
__global__ void prep_w(const float* __restrict__ w2, const float* __restrict__ w3) {
    int idx = blockIdx.x * 256 + threadIdx.x;
    if (idx >= 2 * 9 * CC_ * CC_) return;
    int ic = idx & 127;
    int oc = (idx >> 7) & 127;
    int rest = idx >> 14;
    int tap = rest % 9, layer = rest / 9;
    const float* w = layer ? w3 : w2;
    float v = w[(oc * CC_ + ic) * 9 + tap];
    __half h1 = __float2half_rn(v);
    __half h2 = __float2half_rn(v - __half2float(h1));
    size_t tb = ((size_t)layer * NSTG + tap * 2) * WTE + (size_t)oc * WST;
    g_wsp[tb + ic] = h1;
    g_wsp[tb + WTE + ic] = h2;
    if (ic < WST - 128) {
        __half z = __float2half_rn(0.f);
        g_wsp[tb + 128 + ic] = z;
        g_wsp[tb + WTE + 128 + ic] = z;
    }
}

// ============================================================================
// Tensor-core member conv + fused stats. grid (4, IMG, KMEM).
// fp16 2-split, register-prefetch double-buffered weight staging.
// ============================================================================
__global__ __launch_bounds__(512, 1)
void conv_t(const __half* __restrict__ spkBase,
            const __half* __restrict__ wsp, float* __restrict__ yBase) {
    extern __shared__ __half sm[];
    __half* slab = sm;
    __half* wt = sm + SLAB_E;

    const int tid = threadIdx.x;
    const int img = blockIdx.y;
    const int mem = blockIdx.z;
    const int r0 = blockIdx.x * 8;
    const int wid = tid >> 5, lane = tid & 31;
    const int ocg = (wid & 3) * 32;
    const int pxg = (wid >> 2) * 64;
    const __half z = __float2half_rn(0.f);

    const __half* sb = spkBase + (size_t)mem * TOT + (size_t)img * CC_ * HW;
    for (int job = tid; job < 128 * 10; job += 512) {
        int ic = job / 10, srow = job - 10 * ic;
        int gr = r0 + srow - 1;
        __half* drow = slab + (srow * 34) * ICS + ic;
        if ((unsigned)gr < 32u) {
            const uint4* src = reinterpret_cast<const uint4*>(sb + ic * HW + gr * 32);
            drow[0] = z;
            #pragma unroll
            for (int c8 = 0; c8 < 4; c8++) {
                uint4 u = src[c8];
                const __half* e = reinterpret_cast<const __half*>(&u);
                #pragma unroll
                for (int k = 0; k < 8; k++) drow[(c8 * 8 + k + 1) * ICS] = e[k];
            }
            drow[33 * ICS] = z;
        } else {
            #pragma unroll
            for (int c = 0; c < 34; c++) drow[c * ICS] = z;
        }
    }

    float4 pf[5];
    auto ldW = [&](int s) {
        const float4* src = reinterpret_cast<const float4*>(wsp + (size_t)s * WTE);
        #pragma unroll
        for (int k = 0; k < 5; k++) {
            int i = tid + k * 512;
            if (i < WTE / 8) pf[k] = src[i];
        }
    };
    auto stW = [&](int s) {
        float4* dst = reinterpret_cast<float4*>(wt + (s & 1) * WTE);
        #pragma unroll
        for (int k = 0; k < 5; k++) {
            int i = tid + k * 512;
            if (i < WTE / 8) dst[i] = pf[k];
        }
    };

    float d[2][8][4];
    #pragma unroll
    for (int mt = 0; mt < 2; mt++)
        #pragma unroll
        for (int j = 0; j < 8; j++)
            #pragma unroll
            for (int q = 0; q < 4; q++) d[mt][j][q] = 0.f;

    ldW(0); stW(0);
    __syncthreads();
    for (int s = 0; s < NSTG; s++) {
        if (s + 1 < NSTG) ldW(s + 1);        // LDG latency hidden behind MMA
        const int tap = s >> 1;
        const int dy = tap / 3, dx = tap - 3 * (tap / 3);
        int brow[8];
        #pragma unroll
        for (int j = 0; j < 8; j++) {
            int px = pxg + j * 8 + (lane >> 2);
            brow[j] = (((px >> 5) + dy) * 34 + (px & 31) + dx) * ICS + (lane & 3) * 2;
        }
        const __half* wb = wt + (s & 1) * WTE;
        #pragma unroll
        for (int kc = 0; kc < 8; kc++) {
            const int kb = kc * 16;
            uint32_t a[2][4];
            #pragma unroll
            for (int mt = 0; mt < 2; mt++) {
                const __half* ap =
                    wb + (ocg + mt * 16 + (lane >> 2)) * WST + kb + (lane & 3) * 2;
                a[mt][0] = *reinterpret_cast<const uint32_t*>(ap);
                a[mt][1] = *reinterpret_cast<const uint32_t*>(ap + 8 * WST);
                a[mt][2] = *reinterpret_cast<const uint32_t*>(ap + 8);
                a[mt][3] = *reinterpret_cast<const uint32_t*>(ap + 8 * WST + 8);
            }
            #pragma unroll
            for (int j = 0; j < 8; j++) {
                const __half* bp = slab + brow[j] + kb;
                uint32_t b0 = *reinterpret_cast<const uint32_t*>(bp);
                uint32_t b1 = *reinterpret_cast<const uint32_t*>(bp + 8);
                #pragma unroll
                for (int mt = 0; mt < 2; mt++) {
                    asm volatile(
                        "mma.sync.aligned.m16n8k16.row.col.f32.f16.f16.f32 "
                        "{%0,%1,%2,%3}, {%4,%5,%6,%7}, {%8,%9}, {%0,%1,%2,%3};"
                        : "+f"(d[mt][j][0]), "+f"(d[mt][j][1]),
                          "+f"(d[mt][j][2]), "+f"(d[mt][j][3])
                        : "r"(a[mt][0]), "r"(a[mt][1]), "r"(a[mt][2]),
                          "r"(a[mt][3]), "r"(b0), "r"(b1));
                }
            }
        }
        __syncthreads();
        if (s + 1 < NSTG) {
            stW(s + 1);
            __syncthreads();
        }
    }

    float* yb = yBase + (size_t)mem * TOT + (size_t)img * CC_ * HW + r0 * 32;
    #pragma unroll
    for (int mt = 0; mt < 2; mt++) {
        int m = ocg + mt * 16 + (lane >> 2);
        #pragma unroll
        for (int j = 0; j < 8; j++) {
            int n = pxg + j * 8 + (lane & 3) * 2;
            *reinterpret_cast<float2*>(&yb[m * HW + n]) =
                make_float2(d[mt][j][0], d[mt][j][1]);
            *reinterpret_cast<float2*>(&yb[(m + 8) * HW + n]) =
                make_float2(d[mt][j][2], d[mt][j][3]);
        }
    }

    // fused stats: thread -> quad shfl -> smem -> fp64 atomics (per member)
    float rs[4], rq[4];
    #pragma unroll
    for (int h = 0; h < 4; h++) { rs[h] = 0.f; rq[h] = 0.f; }
    #pragma unroll
    for (int mt = 0; mt < 2; mt++)
        #pragma unroll
        for (int j = 0; j < 8; j++) {
            float a0 = d[mt][j][0], a1 = d[mt][j][1];
            float a2 = d[mt][j][2], a3 = d[mt][j][3];
            rs[mt * 2 + 0] += a0 + a1;
            rq[mt * 2 + 0] += a0 * a0 + a1 * a1;
            rs[mt * 2 + 1] += a2 + a3;
            rq[mt * 2 + 1] += a2 * a2 + a3 * a3;
        }
    #pragma unroll
    for (int h = 0; h < 4; h++) {
        rs[h] += __shfl_xor_sync(~0u, rs[h], 1);
        rs[h] += __shfl_xor_sync(~0u, rs[h], 2);
        rq[h] += __shfl_xor_sync(~0u, rq[h], 1);
        rq[h] += __shfl_xor_sync(~0u, rq[h], 2);
    }
    __syncthreads();
    float* sred = reinterpret_cast<float*>(sm);
    if ((lane & 3) == 0) {
        int r = lane >> 2, g = wid >> 2;
        #pragma unroll
        for (int h = 0; h < 4; h++) {
            int oc = ocg + (h >> 1) * 16 + (h & 1) * 8 + r;
            sred[oc * 4 + g] = rs[h];
            sred[512 + oc * 4 + g] = rq[h];
        }
    }
    __syncthreads();
    if (tid < 256) {
        int oc = tid >> 1;
        const float* p = sred + ((tid & 1) ? 512 : 0) + oc * 4;
        double v = (double)p[0] + (double)p[1] + (double)p[2] + (double)p[3];
        atomicAdd((tid & 1) ? &g_sumsqB[mem * CC_ + oc] : &g_sumsB[mem * CC_ + oc], v);
    }
}

// ============================================================================
// EXACT direct conv (L1 only) — unchanged.
// ============================================================================
__global__ __launch_bounds__(256, 1)
void conv_x(const float* __restrict__ x, const float* __restrict__ w,
            float* __restrict__ y) {
    __shared__ __align__(16) float in_s[8][10][36];
    __shared__ __align__(16) float w_s[72][64];

    const int tid = threadIdx.x;
    const int img = blockIdx.y;
    const int hbase = ((blockIdx.x >> 1) & 3) * 8;
    const int co_base = (blockIdx.x & 1) * 64;
    const float* xb = x + (size_t)img * CC_ * HW;
    float* yb = y + ((size_t)img * CC_ + co_base) * HW;

    const int oc_g = (tid & 7) * 8;
    const int pg = tid >> 3;
    const int cb = (pg & 7) * 4;
    const int rp = pg >> 3;
    const unsigned long long M1 = dup2(-1.0f);

    unsigned long long hi[2][4][4], lo[2][4][4], ch[2][4][4];
    #pragma unroll
    for (int r = 0; r < 2; r++)
        #pragma unroll
        for (int p = 0; p < 4; p++)
            #pragma unroll
            for (int q = 0; q < 4; q++) { hi[r][p][q]=0ull; lo[r][p][q]=0ull; ch[r][p][q]=0ull; }

    for (int ci0 = 0; ci0 < CC_; ci0 += 8) {
        for (int i = tid; i < 8 * 10 * 34; i += 256) {
            int cch = i / 340;
            int rem = i - cch * 340;
            int r = rem / 34;
            int col = rem - r * 34;
            int gr = hbase + r - 1;
            int gc = col - 1;
            float v = 0.f;
            if ((unsigned)gr < 32u && (unsigned)gc < 32u)
                v = xb[(ci0 + cch) * HW + gr * 32 + gc];
            in_s[cch][r][col] = v;
        }
        for (int i = tid; i < 8 * 9 * 64; i += 256) {
            int oc = i / 72;
            int j = i - oc * 72;
            w_s[j][oc] = w[(co_base + oc) * (CC_ * 9) + ci0 * 9 + j];
        }
        __syncthreads();

        #pragma unroll 2
        for (int cch = 0; cch < 8; cch++) {
            #pragma unroll
            for (int dy = 0; dy < 3; dy++) {
                unsigned long long a0[6], a1[6];
                #pragma unroll
                for (int j = 0; j < 6; j++) {
                    a0[j] = dup2(in_s[cch][rp + dy][cb + j]);
                    a1[j] = dup2(in_s[cch][rp + 4 + dy][cb + j]);
                }
                #pragma unroll
                for (int dx = 0; dx < 3; dx++) {
                    const ulonglong2* wp = reinterpret_cast<const ulonglong2*>(
                        &w_s[cch * 9 + dy * 3 + dx][oc_g]);
                    ulonglong2 wv0 = wp[0];
                    ulonglong2 wv1 = wp[1];
                    unsigned long long wq[4] = {wv0.x, wv0.y, wv1.x, wv1.y};
                    #pragma unroll
                    for (int p = 0; p < 4; p++) {
                        #pragma unroll
                        for (int q = 0; q < 4; q++) {
                            fma2(ch[0][p][q], a0[p + dx], wq[q]);
                            fma2(ch[1][p][q], a1[p + dx], wq[q]);
                        }
                    }
                }
            }
        }
        __syncthreads();

        if ((ci0 >> 3) & 1) {
            #pragma unroll
            for (int r = 0; r < 2; r++)
                #pragma unroll
                for (int p = 0; p < 4; p++)
                    #pragma unroll
                    for (int q = 0; q < 4; q++) {
                        unsigned long long c = ch[r][p][q];
                        unsigned long long s = add2(hi[r][p][q], c);
                        unsigned long long zz = add2(s, mul2(hi[r][p][q], M1));
                        unsigned long long e = add2(c, mul2(zz, M1));
                        lo[r][p][q] = add2(lo[r][p][q], e);
                        hi[r][p][q] = s;
                        ch[r][p][q] = 0ull;
                    }
        }
    }

    #pragma unroll
    for (int r = 0; r < 2; r++) {
        int h = hbase + rp + 4 * r;
        #pragma unroll
        for (int q = 0; q < 4; q++) {
            float2 t0 = unp(add2(hi[r][0][q], lo[r][0][q]));
            float2 t1 = unp(add2(hi[r][1][q], lo[r][1][q]));
            float2 t2 = unp(add2(hi[r][2][q], lo[r][2][q]));
            float2 t3 = unp(add2(hi[r][3][q], lo[r][3][q]));
            *reinterpret_cast<float4*>(&yb[(oc_g + 2*q) * HW + h*32 + cb]) =
                make_float4(t0.x, t1.x, t2.x, t3.x);
            *reinterpret_cast<float4*>(&yb[(oc_g + 2*q + 1) * HW + h*32 + cb]) =
                make_float4(t0.y, t1.y, t2.y, t3.y);
        }
    }
}

// ============================================================================
// helpers
// ============================================================================
__global__ void zero_all_k() {
    int t = blockIdx.x * 256 + threadIdx.x;
    if (t < BB * CC_) g_feat[t] = 0.f;
    if (t < CC_) { g_sL1[t] = 0.0; g_qL1[t] = 0.0; }
}
__global__ void zeroB_k() {
    int t = blockIdx.x * 256 + threadIdx.x;
    if (t < KMEM * CC_) { g_sumsB[t] = 0.0; g_sumsqB[t] = 0.0; }
}
__global__ void statsL1_k(const float* __restrict__ y) {
    __shared__ double s1[256], s2[256];
    const int c = blockIdx.x;
    const int g = blockIdx.y;
    const int tid = threadIdx.x;
    double S = 0.0, SS = 0.0;
    const float* base = y + ((size_t)(g * 32) * CC_ + c) * HW;
    for (int i0 = tid; i0 < 32 * HW; i0 += 256 * 8) {
        float s = 0.f, ss = 0.f;
        #pragma unroll
        for (int k = 0; k < 8; k++) {
            int i = i0 + k * 256;
            float v = base[(size_t)(i >> 10) * CC_ * HW + (i & 1023)];
            s += v; ss += v * v;
        }
        S += (double)s; SS += (double)ss;
    }
    s1[tid] = S; s2[tid] = SS;
    __syncthreads();
    for (int o = 128; o > 0; o >>= 1) {
        if (tid < o) { s1[tid] += s1[tid + o]; s2[tid] += s2[tid + o]; }
        __syncthreads();
    }
    if (tid == 0) { atomicAdd(&g_sL1[c], s1[0]); atomicAdd(&g_qL1[c], s2[0]); }
}
__global__ void finalizeL1_k() {
    int c = threadIdx.x;
    if (c >= CC_) return;
    const double invN = 1.0 / (double)(TT * BB * HW);
    double mean = g_sL1[c] * invN;
    double var = g_qL1[c] * invN - mean * mean;
    g_meanL1[c] = (float)mean;
    g_rstdL1[c] = (float)(1.0 / sqrt(var + 1e-5));
}
__global__ void finalizeB_k() {
    int i = blockIdx.x * 128 + threadIdx.x;
    if (i >= KMEM * CC_) return;
    const double invN = 1.0 / (double)(TT * BB * HW);
    double mean = g_sumsB[i] * invN;
    double var = g_sumsqB[i] * invN - mean * mean;
    g_meanB[i] = (float)mean;
    g_rstdB[i] = (float)(1.0 / sqrt(var + 1e-5));
}

// batched member BN + LIF (numerics identical to passing config; fp16 spikes)
template <bool POOL>
__global__ void lifB_k(const float* __restrict__ y, size_t ystride,
                       __half* __restrict__ spk,
                       const float* __restrict__ bnw, const float* __restrict__ bnb,
                       const float* __restrict__ meanp, const float* __restrict__ rstdp,
                       int mstride, unsigned st) {
    const int tid = threadIdx.x;
    const int idx = blockIdx.x * 256 + tid;
    const int m = blockIdx.y;
    const int c = (idx >> 10) & (CC_ - 1);
    const unsigned seed = (unsigned)(m >> 1) * 3u + st;
    const float sg = (m & 1) ? -SIGMA : SIGMA;
    const float mean = meanp[m * mstride + c];
    const float rs = rstdp[m * mstride + c];
    const float wv = bnw[c];
    const float bv = bnb[c];
    const float* yb = y + (size_t)m * ystride;

    float memv = 0.f, s = 0.f, acc = 0.f;
    #pragma unroll
    for (int t = 0; t < TT; t++) {
        float xv = yb[(size_t)t * PLANE + idx];
        xv += gnoise((unsigned)(idx + t * PLANE), seed) * sg;
        float xn = __fmul_rn(__fsub_rn(xv, mean), rs);
        float v  = __fadd_rn(__fmul_rn(xn, wv), bv);
        memv = fmaf(memv, 0.25f * (1.f - s), v);
        s = (memv > 0.5f) ? 1.f : 0.f;
        if (POOL) acc += s;
        else spk[(size_t)m * TOT + (size_t)t * PLANE + idx] = __float2half_rn(s);
    }
    if (POOL) {
        __shared__ float red[256];
        red[tid] = acc;
        __syncthreads();
        for (int o = 128; o > 0; o >>= 1) {
            if (tid < o) red[tid] += red[tid + o];
            __syncthreads();
        }
        if (tid == 0) atomicAdd(&g_feat[idx >> 10], red[0]);
    }
}

__global__ void fc_k(const float* __restrict__ fcw, const float* __restrict__ fcb,
                     float* __restrict__ out) {
    int t = threadIdx.x;
    if (t >= BB * 10) return;
    int b = t / 10, k = t - b * 10;
    const float sc = 1.f / (float)(KMEM * TT * HW);
    float s = 0.f;
    for (int c = 0; c < CC_; c++)
        s = fmaf(g_feat[b * CC_ + c] * sc, fcw[k * CC_ + c], s);
    out[t] = s + fcb[k];
}

// ============================================================================
// launch
// ============================================================================
extern "C" void kernel_launch(void* const* d_in, const int* in_sizes, int n_in,
                              void* d_out, int out_size) {
    const float* inp = (const float*)d_in[0];
    const float* w1  = (const float*)d_in[1];
    const float* w2  = (const float*)d_in[2];
    const float* w3  = (const float*)d_in[3];
    const float* bw1 = (const float*)d_in[4];
    const float* bb1 = (const float*)d_in[5];
    const float* bw2 = (const float*)d_in[6];
    const float* bb2 = (const float*)d_in[7];
    const float* bw3 = (const float*)d_in[8];
    const float* bb3 = (const float*)d_in[9];
    const float* fcw = (const float*)d_in[10];
    const float* fcb = (const float*)d_in[11];
    float* out = (float*)d_out;

    float *bufL1, *bufC, *meanL1, *rstdL1, *meanB, *rstdB;
    __half *bufS, *wsp;
    cudaGetSymbolAddress((void**)&bufL1, g_bufL1);
    cudaGetSymbolAddress((void**)&bufS, g_bufS);
    cudaGetSymbolAddress((void**)&bufC, g_bufC);
    cudaGetSymbolAddress((void**)&wsp, g_wsp);
    cudaGetSymbolAddress((void**)&meanL1, g_meanL1);
    cudaGetSymbolAddress((void**)&rstdL1, g_rstdL1);
    cudaGetSymbolAddress((void**)&meanB, g_meanB);
    cudaGetSymbolAddress((void**)&rstdB, g_rstdB);

    cudaFuncSetAttribute(conv_t, cudaFuncAttributeMaxDynamicSharedMemorySize,
                         CONVT_SMEM);

    const dim3 cgrid(8, IMG);
    const dim3 tgrid(4, IMG, KMEM);
    const dim3 sgrid(CC_, 8);
    const dim3 lgrid(PLANE / 256, KMEM);
    const int zb = (KMEM * CC_ + 255) / 256;

    zero_all_k<<<(BB * CC_ + 255) / 256, 256>>>();
    prep_w<<<(2 * 9 * CC_ * CC_ + 255) / 256, 256>>>(w2, w3);

    // shared L1: exact conv + stats
    conv_x<<<cgrid, 256>>>(inp, w1, bufL1);
    statsL1_k<<<sgrid, 256>>>(bufL1);
    finalizeL1_k<<<1, 128>>>();

    // batched ensemble: L1 lif -> L2 conv/lif -> L3 conv/lif(pool)
    lifB_k<false><<<lgrid, 256>>>(bufL1, 0, bufS, bw1, bb1, meanL1, rstdL1, 0, 0u);

    zeroB_k<<<zb, 256>>>();
    conv_t<<<tgrid, 512, CONVT_SMEM>>>(bufS, wsp, bufC);
    finalizeB_k<<<(KMEM * CC_ + 127) / 128, 128>>>();
    lifB_k<false><<<lgrid, 256>>>(bufC, (size_t)TOT, bufS, bw2, bb2,
                                  meanB, rstdB, CC_, 1u);

    zeroB_k<<<zb, 256>>>();
    conv_t<<<tgrid, 512, CONVT_SMEM>>>(bufS, wsp + (size_t)NSTG * WTE, bufC);
    finalizeB_k<<<(KMEM * CC_ + 127) / 128, 128>>>();
    lifB_k<true><<<lgrid, 256>>>(bufC, (size_t)TOT, nullptr, bw3, bb3,
                                 meanB, rstdB, CC_, 2u);

    fc_k<<<1, 320>>>(fcw, fcb, out);
}